// round 16
// baseline (speedup 1.0000x reference)
#include <cuda_runtime.h>
#include <cuda_fp16.h>
#include <math.h>
#include <stdint.h>

// Problem dims
#define SEQ    4096
#define IDIM   2048
#define HDIM   2048
#define GROWS  8192   // 4*HDIM, PyTorch gate order i,f,g,o
#define OUTD   2048

// Persistent recurrence kernel config
#define UPC      14
#define NCTA     147
#define RTHREADS 1024             // 32 warps = 4 m-tiles x 8 k-groups
#define MAXROWS  (4*UPC)          // 56
// fragment-tile weight layout: 3 full 16-row tiles (64KB) + compact 8-row tile (32KB)
#define SW_BYTES 229376

// mma.sync GEMM config
#define BM 128
#define BN 128
#define BK 32
#define NCH    (IDIM/BK)          // 64 k-chunks
#define STAGES 4
#define APAD   40                 // halves per SMEM row (32 + 8 pad) -> 80B stride
#define STG_A  (BM*APAD*2)        // 10240 B
#define STG_B  (2*STG_A)          // 20480 B per stage (A then B)
#define GEMM_SMEM (STAGES*STG_B)  // 81920 B

// -------- device scratch (static allocation only) --------
__device__ float    g_xg[(size_t)SEQ * GROWS];   // 128 MB
__device__ __half   g_xh[(size_t)SEQ * IDIM];    // 16 MB  x in fp16
__device__ __half   g_wh[(size_t)GROWS * IDIM];  // 32 MB  W_ih in fp16
__device__ float    g_h[2][HDIM];                // fp32 h (final FC reads this)
__device__ __align__(16) uint32_t g_hp[2][HDIM/2]; // fp16 h, 4x4-word-transposed
__device__ unsigned g_bar  = 0u;                 // monotonic arrival counter
__device__ unsigned g_base = 0u;                 // epoch base across graph replays

// ---------------- PTX helpers (all sm_80+; no arch-suffix features) ----------
__device__ __forceinline__ uint32_t smem_u32(const void* p) {
    return (uint32_t)__cvta_generic_to_shared(p);
}
__device__ __forceinline__ void cp_async16(uint32_t dst, const void* src) {
    asm volatile("cp.async.cg.shared.global [%0], [%1], 16;" :: "r"(dst), "l"(src));
}
__device__ __forceinline__ void ldmatrix_x4(uint32_t* r, uint32_t addr) {
    asm volatile("ldmatrix.sync.aligned.m8n8.x4.shared.b16 {%0,%1,%2,%3}, [%4];"
                 : "=r"(r[0]), "=r"(r[1]), "=r"(r[2]), "=r"(r[3]) : "r"(addr));
}
__device__ __forceinline__ void mma16816(float* c, const uint32_t* a,
                                         uint32_t b0, uint32_t b1) {
    asm volatile(
        "mma.sync.aligned.m16n8k16.row.col.f32.f16.f16.f32 "
        "{%0,%1,%2,%3}, {%4,%5,%6,%7}, {%8,%9}, {%0,%1,%2,%3};"
        : "+f"(c[0]), "+f"(c[1]), "+f"(c[2]), "+f"(c[3])
        : "r"(a[0]), "r"(a[1]), "r"(a[2]), "r"(a[3]), "r"(b0), "r"(b1));
}
__device__ __forceinline__ float sig_fast(float x) {
    float r;
    asm("rcp.approx.f32 %0, %1;" : "=f"(r) : "f"(1.f + __expf(-x)));
    return r;
}
__device__ __forceinline__ float tanh_fast(float x) {
    float r;
    asm("rcp.approx.f32 %0, %1;" : "=f"(r) : "f"(1.f + __expf(-2.f * x)));
    return fmaf(2.f, r, -1.f);
}

// ============================================================================
// Kernel 0: fp32 -> fp16 conversion (x and W_ih)
// ============================================================================
__global__ void __launch_bounds__(256)
f2h_kernel(const float* __restrict__ src, __half* __restrict__ dst, int n)
{
    int i = (blockIdx.x * 256 + threadIdx.x) * 8;
    if (i >= n) return;
    const float4 a = *(const float4*)(src + i);
    const float4 b = *(const float4*)(src + i + 4);
    __half2 h0 = __floats2half2_rn(a.x, a.y);
    __half2 h1 = __floats2half2_rn(a.z, a.w);
    __half2 h2 = __floats2half2_rn(b.x, b.y);
    __half2 h3 = __floats2half2_rn(b.z, b.w);
    uint4 o;
    o.x = *(uint32_t*)&h0; o.y = *(uint32_t*)&h1;
    o.z = *(uint32_t*)&h2; o.w = *(uint32_t*)&h3;
    *(uint4*)(dst + i) = o;
}

// ============================================================================
// Kernel 1: xg = x @ W_ih^T + b_ih + b_hh  via mma.sync.m16n8k16 (fp16->fp32).
// 128x128 tile / CTA, 8 warps of 64x32, 4-stage cp.async pipeline over K.
// ============================================================================
__global__ void __launch_bounds__(256, 1)
gemm_xg_mma(const float* __restrict__ b1, const float* __restrict__ b2)
{
    extern __shared__ char dynsmem[];
    __shared__ float s_bias[BN];

    const int tid    = threadIdx.x;
    const int lane   = tid & 31;
    const int wid    = tid >> 5;
    const int warp_m = wid >> 2;            // 0..1
    const int warp_n = wid & 3;             // 0..3
    const int mw     = warp_m * 64;
    const int nb     = warp_n * 32;
    const int n0     = blockIdx.x * BN;
    const int m0     = blockIdx.y * BM;

    const uint32_t sm0 = smem_u32(dynsmem);

    if (tid < BN) s_bias[tid] = b1[n0 + tid] + b2[n0 + tid];

    const __half* gA = g_xh + (size_t)m0 * IDIM;
    const __half* gB = g_wh + (size_t)n0 * IDIM;

    auto load_chunk = [&](int kc) {
        const uint32_t base = sm0 + (uint32_t)(kc & (STAGES - 1)) * STG_B;
        const int k0 = kc * BK;
#pragma unroll
        for (int part = 0; part < 4; ++part) {
            const int idx = part * 256 + tid;           // 0..1023
            const int row = (idx >> 2) & 127;
            const int seg = idx & 3;
            const uint32_t doff = (uint32_t)(row * (APAD * 2) + seg * 16);
            if (idx < 512)
                cp_async16(base + doff, gA + (size_t)row * IDIM + k0 + seg * 8);
            else
                cp_async16(base + STG_A + doff, gB + (size_t)row * IDIM + k0 + seg * 8);
        }
        asm volatile("cp.async.commit_group;" ::: "memory");
    };

    float acc[4][4][4];
#pragma unroll
    for (int mi = 0; mi < 4; ++mi)
#pragma unroll
        for (int ni = 0; ni < 4; ++ni)
#pragma unroll
            for (int q = 0; q < 4; ++q) acc[mi][ni][q] = 0.f;

    load_chunk(0);
    load_chunk(1);
    load_chunk(2);

    for (int kc = 0; kc < NCH; ++kc) {
        const int pf = kc + STAGES - 1;
        if (pf < NCH) load_chunk(pf);

        if (kc <= NCH - STAGES)
            asm volatile("cp.async.wait_group %0;" :: "n"(STAGES - 1) : "memory");
        else if (kc == NCH - 3)
            asm volatile("cp.async.wait_group 2;" ::: "memory");
        else if (kc == NCH - 2)
            asm volatile("cp.async.wait_group 1;" ::: "memory");
        else
            asm volatile("cp.async.wait_group 0;" ::: "memory");
        __syncthreads();

        const uint32_t as_ = sm0 + (uint32_t)(kc & (STAGES - 1)) * STG_B;
        const uint32_t bs_ = as_ + STG_A;

#pragma unroll
        for (int s = 0; s < 2; ++s) {               // two k16 steps
            uint32_t af[4][4];
#pragma unroll
            for (int mi = 0; mi < 4; ++mi) {
                const uint32_t addr = as_
                    + (uint32_t)(mw + mi * 16 + (lane & 15)) * (APAD * 2)
                    + (uint32_t)(s * 16 + ((lane >> 4) << 3)) * 2;
                ldmatrix_x4(af[mi], addr);
            }
            uint32_t bf[2][4];
#pragma unroll
            for (int g = 0; g < 2; ++g) {
                const uint32_t addr = bs_
                    + (uint32_t)(nb + g * 16 + (lane & 7) + (((lane >> 4) & 1) << 3)) * (APAD * 2)
                    + (uint32_t)(s * 16 + (((lane >> 3) & 1) << 3)) * 2;
                ldmatrix_x4(bf[g], addr);
            }
#pragma unroll
            for (int mi = 0; mi < 4; ++mi)
#pragma unroll
                for (int ni = 0; ni < 4; ++ni)
                    mma16816(acc[mi][ni], af[mi],
                             bf[ni >> 1][(ni & 1) * 2],
                             bf[ni >> 1][(ni & 1) * 2 + 1]);
        }
        __syncthreads();
    }

#pragma unroll
    for (int mi = 0; mi < 4; ++mi) {
        const int r0 = m0 + mw + mi * 16 + (lane >> 2);
#pragma unroll
        for (int ni = 0; ni < 4; ++ni) {
            const int c = nb + ni * 8 + (lane & 3) * 2;
            const float bb0 = s_bias[c];
            const float bb1 = s_bias[c + 1];
            float2 v0, v1;
            v0.x = acc[mi][ni][0] + bb0; v0.y = acc[mi][ni][1] + bb1;
            v1.x = acc[mi][ni][2] + bb0; v1.y = acc[mi][ni][3] + bb1;
            *(float2*)&g_xg[(size_t)r0 * GROWS + n0 + c]       = v0;
            *(float2*)&g_xg[(size_t)(r0 + 8) * GROWS + n0 + c] = v1;
        }
    }
}

// ============================================================================
// Kernel 2: persistent LSTM recurrence — TENSOR-CORE matvec.
// Weights in SMEM as ldmatrix-ready 8x8 fragment tiles (3 full 16-row m-tiles
// @64KB + compact 8-row tile @32KB = 229376B). Warp (mt,kg): 16 k16-chunks of
// mma.m16n8k16, h replicated across all 8 N columns (B fragment = broadcast
// LDG.128 from the 4x4-word-transposed g_hp). C fragment accumulates over k
// in fp32 — no shfl reduction. Barrier/gate identical to round 15.
// ============================================================================
__global__ void __launch_bounds__(RTHREADS, 1)
lstm_persistent(const float* __restrict__ W_hh)
{
    extern __shared__ __half sw[];
    __shared__ float s_part8[MAXROWS][8];   // [row][kgroup] partial sums
    __shared__ float s_c[UPC];

    const int tid   = threadIdx.x;
    const int wid   = tid >> 5;
    const int lane  = tid & 31;
    const int mt    = wid >> 3;           // 0..3  m-tile
    const int kg    = wid & 7;            // 0..7  k-group (256 k elems)
    const int cta   = blockIdx.x;
    const int u0    = cta * UPC;
    const int nu    = (HDIM - u0 < UPC) ? (HDIM - u0) : UPC;
    const int nrows = 4 * nu;

    // ---- one-time: W_hh rows -> SMEM fragment-tile layout, fp16 ----
    // full tiles mt<3: off = mt*65536 + kc*512 + j*128 + (ri%8)*16, j = ri/8 + 2*kh
    // compact tile (rows 48-55): off = 196608 + kc*256 + kh*128 + (ri%8)*16
    for (int idx = tid; idx < nrows * (HDIM / 8); idx += RTHREADS) {
        const int r  = idx >> 8;          // local row (256 segs per row)
        const int s  = idx & 255;
        const int k  = s << 3;
        const int gate = r / nu;
        const int u    = r - gate * nu;
        const int mtr  = r >> 4;
        const int ri   = r & 15;
        const int kc   = s >> 1;
        const int kh   = s & 1;
        uint32_t off;
        if (mtr < 3)
            off = (uint32_t)mtr * 65536u + (uint32_t)kc * 512u
                + (uint32_t)(((ri >> 3) + (kh << 1)) << 7) + (uint32_t)((ri & 7) << 4);
        else
            off = 196608u + (uint32_t)kc * 256u + (uint32_t)(kh << 7)
                + (uint32_t)((ri & 7) << 4);
        const float* wp = &W_hh[(size_t)(gate * HDIM + u0 + u) * HDIM + k];
        const float4 v0 = *(const float4*)(wp);
        const float4 v1 = *(const float4*)(wp + 4);
        __half2 q0 = __floats2half2_rn(v0.x, v0.y);
        __half2 q1 = __floats2half2_rn(v0.z, v0.w);
        __half2 q2 = __floats2half2_rn(v1.x, v1.y);
        __half2 q3 = __floats2half2_rn(v1.z, v1.w);
        uint4 o;
        o.x = *(uint32_t*)&q0; o.y = *(uint32_t*)&q1;
        o.z = *(uint32_t*)&q2; o.w = *(uint32_t*)&q3;
        *(uint4*)((char*)sw + off) = o;
    }
    if (tid < UPC) s_c[tid] = 0.f;
    for (int i = tid; i < MAXROWS * 8; i += RTHREADS) ((float*)s_part8)[i] = 0.f;

    unsigned base = 0u;
    if (tid == 0) base = *(volatile unsigned*)&g_base;
    __syncthreads();

    // per-warp constant ldmatrix base + chunk stride
    const bool     t3      = (mt == 3);
    const uint32_t cstride = t3 ? 256u : 512u;
    const uint32_t wbase   = smem_u32(sw)
        + (t3 ? (196608u + (uint32_t)kg * 16u * 256u
                 + (uint32_t)((lane >> 4) << 7) + (uint32_t)((lane & 7) << 4))
              : ((uint32_t)mt * 65536u + (uint32_t)kg * 16u * 512u
                 + (uint32_t)(lane << 4)));

    for (int t = 0; t < SEQ; ++t) {
        // prefetch xg (independent of h)
        float xgv0 = 0.f, xgv1 = 0.f, xgv2 = 0.f, xgv3 = 0.f;
        if (tid < nu) {
            const float* xp = g_xg + (size_t)t * GROWS + u0 + tid;
            xgv0 = xp[0 * HDIM];
            xgv1 = xp[1 * HDIM];
            xgv2 = xp[2 * HDIM];
            xgv3 = xp[3 * HDIM];
        }

        if (t > 0) {
            // arrival for this barrier was issued at the end of step t-1's gate
            if (tid == 0) {
                const unsigned tgt = base + (unsigned)NCTA * (unsigned)t;
                while ((int)(*(volatile unsigned*)&g_bar - tgt) < 0) { }
                __threadfence();                       // acquire + IVALL: fresh L1
            }
            __syncthreads();   // (B)

            // ---- tensor-core matvec: 16 chunks of m16n8k16, k-accumulated ----
            const uint32_t* hpb = g_hp[t & 1] + kg * 128 + ((lane & 3) << 2);
            float c[4] = {0.f, 0.f, 0.f, 0.f};
            uint32_t a[4];
#pragma unroll
            for (int cp = 0; cp < 8; ++cp) {           // chunk pairs
                const uint4 bv = *(const uint4*)(hpb + cp * 16);
                ldmatrix_x4(a, wbase + (uint32_t)(2 * cp) * cstride);
                mma16816(c, a, bv.x, bv.y);
                ldmatrix_x4(a, wbase + (uint32_t)(2 * cp + 1) * cstride);
                mma16816(c, a, bv.z, bv.w);
            }
            if ((lane & 3) == 0) {
                const int row = mt * 16 + (lane >> 2);
                s_part8[row][kg] = c[0];
                if (!t3) s_part8[row + 8][kg] = c[2];
            }
        }
        __syncthreads();       // (C) s_part8 complete

        // ---- gate combine + state update + permuted fp16 h broadcast ----
        if (wid == 0) {
            float hv = 0.f;
            const bool act = (lane < nu);
            if (act) {
                const int r0 = 0 * nu + lane, r1 = 1 * nu + lane;
                const int r2 = 2 * nu + lane, r3 = 3 * nu + lane;
                const float4 pi0 = *(const float4*)&s_part8[r0][0];
                const float4 pi1 = *(const float4*)&s_part8[r0][4];
                const float4 pf0 = *(const float4*)&s_part8[r1][0];
                const float4 pf1 = *(const float4*)&s_part8[r1][4];
                const float4 pg0 = *(const float4*)&s_part8[r2][0];
                const float4 pg1 = *(const float4*)&s_part8[r2][4];
                const float4 po0 = *(const float4*)&s_part8[r3][0];
                const float4 po1 = *(const float4*)&s_part8[r3][4];
                const float gi = xgv0 + ((pi0.x + pi0.y) + (pi0.z + pi0.w))
                                      + ((pi1.x + pi1.y) + (pi1.z + pi1.w));
                const float gf = xgv1 + ((pf0.x + pf0.y) + (pf0.z + pf0.w))
                                      + ((pf1.x + pf1.y) + (pf1.z + pf1.w));
                const float gg = xgv2 + ((pg0.x + pg0.y) + (pg0.z + pg0.w))
                                      + ((pg1.x + pg1.y) + (pg1.z + pg1.w));
                const float go = xgv3 + ((po0.x + po0.y) + (po0.z + po0.w))
                                      + ((po1.x + po1.y) + (po1.z + po1.w));
                const float ig = sig_fast(gi);
                const float fg = sig_fast(gf);
                const float g2 = tanh_fast(gg);
                const float og = sig_fast(go);
                const float cc = fg * s_c[lane] + ig * g2;
                s_c[lane] = cc;
                hv = og * tanh_fast(cc);
                g_h[(t + 1) & 1][u0 + lane] = hv;       // fp32 for final FC
            }
            // permuted fp16 broadcast: word w -> hp[b*16 + 4*(w%16 & 3) + (w%16)/4]
            const unsigned hb16 = (unsigned)__half_as_ushort(__float2half_rn(hv));
            const unsigned hi   = __shfl_down_sync(0xffffffffu, hb16, 1);
            if (act && !(lane & 1)) {
                const int w  = (u0 >> 1) + (lane >> 1);
                const int b  = w >> 4;
                const int wb = w & 15;
                g_hp[(t + 1) & 1][(b << 4) + ((wb & 3) << 2) + (wb >> 2)]
                    = hb16 | (hi << 16);
            }
            __syncwarp();
            if (lane == 0)
                asm volatile("red.release.gpu.global.add.u32 [%0], %1;"
                             :: "l"(&g_bar), "r"(1u) : "memory");
        }
    }

    // epilogue: arrivals total SEQ per CTA; wait for all, then update epoch
    if (tid == 0) {
        const unsigned tgt = base + (unsigned)NCTA * (unsigned)SEQ;
        while ((int)(*(volatile unsigned*)&g_bar - tgt) < 0) { }
        if (cta == 0) *(volatile unsigned*)&g_base = tgt;
    }
}

// ============================================================================
// Kernel 3: out = h_last @ W_fc^T + b_fc   (h_last in g_h[0]; SEQ even)
// ============================================================================
__global__ void __launch_bounds__(256)
fc_kernel(const float* __restrict__ Wfc, const float* __restrict__ bfc,
          float* __restrict__ out)
{
    const int o    = blockIdx.x * 8 + (threadIdx.x >> 5);
    const int lane = threadIdx.x & 31;
    const float* hb = g_h[0];
    const float* wr = Wfc + (size_t)o * HDIM;
    float acc = 0.f;
#pragma unroll
    for (int i = 0; i < 16; ++i) {
        const int k = i * 128 + lane * 4;
        const float4 w  = *(const float4*)&wr[k];
        const float4 h4 = *(const float4*)&hb[k];
        acc += w.x * h4.x + w.y * h4.y + w.z * h4.z + w.w * h4.w;
    }
#pragma unroll
    for (int off = 16; off; off >>= 1)
        acc += __shfl_xor_sync(0xffffffffu, acc, off);
    if (lane == 0) out[o] = acc + bfc[o];
}

// ============================================================================
extern "C" void kernel_launch(void* const* d_in, const int* in_sizes, int n_in,
                              void* d_out, int out_size)
{
    const float* x   = (const float*)d_in[0];
    const float* Wih = (const float*)d_in[1];
    const float* Whh = (const float*)d_in[2];
    const float* bih = (const float*)d_in[3];
    const float* bhh = (const float*)d_in[4];
    const float* Wfc = (const float*)d_in[5];
    const float* bfc = (const float*)d_in[6];
    float* out = (float*)d_out;

    static __half* p_xh = nullptr;
    static __half* p_wh = nullptr;
    if (!p_xh) {
        cudaGetSymbolAddress((void**)&p_xh, g_xh);
        cudaGetSymbolAddress((void**)&p_wh, g_wh);
        cudaFuncSetAttribute(gemm_xg_mma,
                             cudaFuncAttributeMaxDynamicSharedMemorySize,
                             (int)GEMM_SMEM);
        cudaFuncSetAttribute(lstm_persistent,
                             cudaFuncAttributeMaxDynamicSharedMemorySize,
                             (int)SW_BYTES);
    }

    f2h_kernel<<<(SEQ * IDIM / 8 + 255) / 256, 256>>>(x, p_xh, SEQ * IDIM);
    f2h_kernel<<<(GROWS * IDIM / 8 + 255) / 256, 256>>>(Wih, p_wh, GROWS * IDIM);
    gemm_xg_mma<<<dim3(GROWS / BN, SEQ / BM), 256, GEMM_SMEM>>>(bih, bhh);
    lstm_persistent<<<NCTA, RTHREADS, SW_BYTES>>>(Whh);
    fc_kernel<<<OUTD / 8, 256>>>(Wfc, bfc, out);
}